// round 16
// baseline (speedup 1.0000x reference)
#include <cuda_runtime.h>
#include <cuda_bf16.h>
#include <math.h>

#define NN      200000
#define NP      200192      // padded: 128*1564 for GEMM tiling
#define EE      300000
#define NE3     (3 * EE)
#define BBATCH  64
#define HIDDEN  128
#define NREL    3
#define NHEAD   4
#define F7      896         // q | kt0..2 | vt0..2  (7 * 128)
#define INV_SQRT_D 0.17677669529663687f
#define NB_SCAN 196         // ceil(NN / 1024)

// ---------------- scratch (device globals; no allocations allowed) ----------
__device__ __align__(16) __nv_bfloat16  g_hb[NP * HIDDEN];         // h (bf16 only)
__device__ __align__(16) __nv_bfloat16  g_q[(size_t)NP * 128];     // q (dst-indexed)
__device__ __align__(16) __nv_bfloat16  g_kv[(size_t)NP * 768];    // [node][rel][kt128|vt128]
__device__ __align__(16) __nv_bfloat16  g_aggb[NP * HIDDEN];       // gelu(agg) bf16
__device__ __align__(16) __nv_bfloat16  g_Wcb[F7 * HIDDEN];        // N-major bf16
__device__ __align__(16) __nv_bfloat16  g_Wrb[HIDDEN * HIDDEN];    // N-major bf16
__device__ float                        g_bc[F7];
__device__ float                        g_poolsum[2 * BBATCH * HIDDEN];
__device__ float                        g_poolcnt[2 * BBATCH];
// CSR (rebuilt every launch)
__device__ int                          g_deg[NN];
__device__ int                          g_rowptr[NN];
__device__ int                          g_cur[NN];
__device__ int                          g_bsum[256];
__device__ int                          g_eidx[NE3];               // src | rel<<18

// ---------------- input embedding -------------------------------------------
__global__ void k_embed(const float* __restrict__ x, const int* __restrict__ ast,
                        const float* __restrict__ emb, const float* __restrict__ Win,
                        const float* __restrict__ binp) {
    __shared__ float Ws[69 * 128];
    __shared__ float iv[69];
    for (int i = threadIdx.x; i < 69 * 128; i += blockDim.x) Ws[i] = Win[i];
    int j = threadIdx.x;  // 128 threads
    for (int n = blockIdx.x; n < NN; n += gridDim.x) {
        __syncthreads();
        if (j < 64)       iv[j] = emb[(size_t)ast[n] * 64 + j];
        else if (j < 69)  iv[j] = x[(size_t)n * 5 + (j - 64)];
        __syncthreads();
        float acc = binp[j];
        #pragma unroll
        for (int i = 0; i < 69; i++) acc += iv[i] * Ws[i * 128 + j];
        g_hb[(size_t)n * 128 + j] = __float2bfloat16(acc);
    }
}

// ---------------- composite weights + Wout transpose (merged) ---------------
__global__ void k_wcomp(const float* __restrict__ Wkqv, const float* __restrict__ bkqv,
                        const float* __restrict__ Wk_rel, const float* __restrict__ Wv_rel,
                        const float* __restrict__ Wout_l, int l) {
    int i = threadIdx.x;    // 0..127
    if (blockIdx.x >= 896) {               // tail 128 blocks: Wout transpose
        int bb = blockIdx.x - 896;         // k index
        g_Wrb[(size_t)i * 128 + bb] = __float2bfloat16(Wout_l[bb * 128 + i]);
        return;
    }
    int col = blockIdx.x;   // 0..895 (output col)
    const float* Wl = Wkqv + (size_t)l * 128 * 384;
    const float* bl = bkqv + l * 384;
    int pl = col >> 7;      // plane: 0=q, 1..3=kt, 4..6=vt
    float wv, bv;
    if (pl == 0) {
        wv = Wl[(size_t)i * 384 + 128 + col];
        bv = bl[128 + col];
    } else {
        int cc = col & 127, h = cc >> 5, f = cc & 31;
        int rel   = (pl <= 3) ? (pl - 1) : (pl - 4);
        int kvoff = (pl <= 3) ? 0 : 256;
        const float* Wr = ((pl <= 3) ? Wk_rel : Wv_rel) + (size_t)((l * 3 + rel) * 4 + h) * 1024;
        float acc = 0.f, bacc = 0.f;
        #pragma unroll
        for (int d = 0; d < 32; d++) {
            float wr = Wr[d * 32 + f];
            acc  += Wl[(size_t)i * 384 + kvoff + h * 32 + d] * wr;
            bacc += bl[kvoff + h * 32 + d] * wr;
        }
        wv = acc; bv = bacc;
    }
    g_Wcb[(size_t)col * 128 + i] = __float2bfloat16(wv);
    if (i == 0) g_bc[col] = bv;
}

__global__ void k_init_pool() {
    int i = blockIdx.x * blockDim.x + threadIdx.x;
    if (i < 2 * BBATCH * HIDDEN) g_poolsum[i] = 0.f;
    if (i < 2 * BBATCH) g_poolcnt[i] = 0.f;
}

// ---------------- CSR build (once per launch) --------------------------------
__global__ void k_csr_zero() {
    int i = blockIdx.x * blockDim.x + threadIdx.x;
    if (i < NN) g_deg[i] = 0;
}

__global__ void k_csr_hist(const int* __restrict__ ei0, const int* __restrict__ ei1,
                           const int* __restrict__ ei2) {
    int idx = blockIdx.x * blockDim.x + threadIdx.x;
    if (idx >= NE3) return;
    int r = idx / EE, e = idx - r * EE;
    const int* ei = (r == 0) ? ei0 : ((r == 1) ? ei1 : ei2);
    atomicAdd(&g_deg[__ldg(ei + EE + e)], 1);
}

__global__ void k_csr_scan1() {
    __shared__ int ss[256];
    int b = blockIdx.x, t = threadIdx.x;
    int base = b * 1024 + t * 4;
    int v[4], tot = 0;
    #pragma unroll
    for (int i = 0; i < 4; i++) {
        v[i] = (base + i < NN) ? g_deg[base + i] : 0;
        tot += v[i];
    }
    ss[t] = tot; __syncthreads();
    for (int off = 1; off < 256; off <<= 1) {
        int x = (t >= off) ? ss[t - off] : 0;
        __syncthreads();
        ss[t] += x;
        __syncthreads();
    }
    int run = ss[t] - tot;
    #pragma unroll
    for (int i = 0; i < 4; i++) {
        if (base + i < NN) g_rowptr[base + i] = run;
        run += v[i];
    }
    if (t == 255) g_bsum[b] = ss[255];
}

__global__ void k_csr_scan2() {
    __shared__ int ss[256];
    int t = threadIdx.x;
    int own = (t < NB_SCAN) ? g_bsum[t] : 0;
    ss[t] = own; __syncthreads();
    for (int off = 1; off < 256; off <<= 1) {
        int x = (t >= off) ? ss[t - off] : 0;
        __syncthreads();
        ss[t] += x;
        __syncthreads();
    }
    if (t < NB_SCAN) g_bsum[t] = ss[t] - own;
}

__global__ void k_csr_scan3() {
    int b = blockIdx.x, t = threadIdx.x;
    int off = g_bsum[b];
    int base = b * 1024 + t * 4;
    #pragma unroll
    for (int i = 0; i < 4; i++) {
        if (base + i < NN) {
            int rp = g_rowptr[base + i] + off;
            g_rowptr[base + i] = rp;
            g_cur[base + i] = rp;
        }
    }
}

__global__ void k_csr_fill(const int* __restrict__ ei0, const int* __restrict__ ei1,
                           const int* __restrict__ ei2) {
    int idx = blockIdx.x * blockDim.x + threadIdx.x;
    if (idx >= NE3) return;
    int r = idx / EE, e = idx - r * EE;
    const int* ei = (r == 0) ? ei0 : ((r == 1) ? ei1 : ei2);
    int src = __ldg(ei + e), dst = __ldg(ei + EE + e);
    int pos = atomicAdd(&g_cur[dst], 1);
    g_eidx[pos] = src | (r << 18);
}

// ---------------- pipelined BF16 tensor-core GEMM core ----------------------
#define BK    32
#define HSTR  40
#define SA_H  (128 * HSTR)
#define SB_H  (128 * HSTR)
#define SB_OFF (4 * SA_H)
#define GEMM_SMEM ((SB_OFF + 4 * SB_H) * 2) // 81920 B
#define EPI_STR 136                          // epilogue staging stride (halves)

__device__ __forceinline__ void mma_bf16(float c[4], const unsigned int a[4],
                                         const unsigned int b[2]) {
    asm volatile(
        "mma.sync.aligned.m16n8k16.row.col.f32.bf16.bf16.f32 "
        "{%0,%1,%2,%3}, {%4,%5,%6,%7}, {%8,%9}, {%0,%1,%2,%3};"
        : "+f"(c[0]), "+f"(c[1]), "+f"(c[2]), "+f"(c[3])
        : "r"(a[0]), "r"(a[1]), "r"(a[2]), "r"(a[3]), "r"(b[0]), "r"(b[1]));
}
__device__ __forceinline__ void cpasync16(unsigned int dst, const void* src) {
    asm volatile("cp.async.cg.shared.global [%0], [%1], 16;" :: "r"(dst), "l"(src));
}
#define CP_COMMIT() asm volatile("cp.async.commit_group;")
#define CP_WAIT(N)  asm volatile("cp.async.wait_group %0;" :: "n"(N))

__device__ __forceinline__ void gemm_load_stage(unsigned int smb, int s, int kt,
                                                const __nv_bfloat16* __restrict__ A,
                                                const __nv_bfloat16* __restrict__ Bt,
                                                int row0, int col0, int t) {
    #pragma unroll
    for (int i = 0; i < 2; i++) {
        int idx = t + i * 256;
        int row = idx >> 2, c8 = (idx & 3) << 3;
        unsigned int dst = smb + (unsigned int)(s * SA_H + row * HSTR + c8) * 2u;
        cpasync16(dst, A + (size_t)(row0 + row) * 128 + kt * BK + c8);
    }
    #pragma unroll
    for (int i = 0; i < 2; i++) {
        int idx = t + i * 256;
        int row = idx >> 2, c8 = (idx & 3) << 3;
        unsigned int dst = smb + (unsigned int)(SB_OFF + s * SB_H + row * HSTR + c8) * 2u;
        cpasync16(dst, Bt + (size_t)(col0 + row) * 128 + kt * BK + c8);
    }
    CP_COMMIT();
}

__device__ __forceinline__ void gemm_compute_stage(const __nv_bfloat16* __restrict__ sm,
                                                   int s, int wm, int wn, int gid, int tig,
                                                   float c[4][4][4]) {
    const __nv_bfloat16* As = sm + s * SA_H;
    const __nv_bfloat16* Bs = sm + SB_OFF + s * SB_H;
    #pragma unroll
    for (int k16 = 0; k16 < 2; k16++) {
        int kk = k16 * 16;
        unsigned int a[4][4];
        #pragma unroll
        for (int mt = 0; mt < 4; mt++) {
            int m0 = wm * 64 + mt * 16 + gid;
            a[mt][0] = *(const unsigned int*)(As + m0 * HSTR + kk + tig * 2);
            a[mt][1] = *(const unsigned int*)(As + (m0 + 8) * HSTR + kk + tig * 2);
            a[mt][2] = *(const unsigned int*)(As + m0 * HSTR + kk + 8 + tig * 2);
            a[mt][3] = *(const unsigned int*)(As + (m0 + 8) * HSTR + kk + 8 + tig * 2);
        }
        unsigned int b[4][2];
        #pragma unroll
        for (int nt = 0; nt < 4; nt++) {
            int n0 = wn * 32 + nt * 8 + gid;
            b[nt][0] = *(const unsigned int*)(Bs + n0 * HSTR + kk + tig * 2);
            b[nt][1] = *(const unsigned int*)(Bs + n0 * HSTR + kk + 8 + tig * 2);
        }
        #pragma unroll
        for (int mt = 0; mt < 4; mt++)
            #pragma unroll
            for (int nt = 0; nt < 4; nt++)
                mma_bf16(c[mt][nt], a[mt], b[nt]);
    }
}

#define GEMM_PIPELINE(A, Bt, row0, col0)                                   \
    gemm_load_stage(smb, 0, 0, A, Bt, row0, col0, t);                      \
    gemm_load_stage(smb, 1, 1, A, Bt, row0, col0, t);                      \
    gemm_load_stage(smb, 2, 2, A, Bt, row0, col0, t);                      \
    gemm_load_stage(smb, 3, 3, A, Bt, row0, col0, t);

#define GEMM_MAINLOOP()                                                    \
    CP_WAIT(3); __syncthreads(); gemm_compute_stage(smh, 0, wm, wn, gid, tig, c); \
    CP_WAIT(2); __syncthreads(); gemm_compute_stage(smh, 1, wm, wn, gid, tig, c); \
    CP_WAIT(1); __syncthreads(); gemm_compute_stage(smh, 2, wm, wn, gid, tig, c); \
    CP_WAIT(0); __syncthreads(); gemm_compute_stage(smh, 3, wm, wn, gid, tig, c);

// ---------------- feat GEMM: h@Wc -> q/kt/vt planes --------------------------
__global__ __launch_bounds__(256, 2) void k_gemm_feat_tc() {
    extern __shared__ __nv_bfloat16 smh[];
    __shared__ float s_bias[128];
    unsigned int smb = (unsigned int)__cvta_generic_to_shared(smh);
    int t = threadIdx.x;
    int row0 = blockIdx.y * 128;
    int col0 = blockIdx.x * 128;

    GEMM_PIPELINE(g_hb, g_Wcb, row0, col0)

    if (t < 128) s_bias[t] = g_bc[col0 + t];

    int wid = t >> 5, lane = t & 31;
    int wm = wid >> 2, wn = wid & 3;
    int gid = lane >> 2, tig = lane & 3;
    float c[4][4][4];
    #pragma unroll
    for (int mt = 0; mt < 4; mt++)
        #pragma unroll
        for (int nt = 0; nt < 4; nt++)
            #pragma unroll
            for (int q = 0; q < 4; q++) c[mt][nt][q] = 0.f;

    GEMM_MAINLOOP()

    // epilogue: stage in smem -> coalesced uint4 writes
    __syncthreads();
    #pragma unroll
    for (int mt = 0; mt < 4; mt++) {
        #pragma unroll
        for (int nt = 0; nt < 4; nt++) {
            int rloc = wm * 64 + mt * 16 + gid;
            int cc = wn * 32 + nt * 8 + tig * 2;
            float b0 = s_bias[cc], b1 = s_bias[cc + 1];
            *(__nv_bfloat162*)(smh + rloc * EPI_STR + cc) =
                __float22bfloat162_rn(make_float2(c[mt][nt][0] + b0, c[mt][nt][1] + b1));
            *(__nv_bfloat162*)(smh + (rloc + 8) * EPI_STR + cc) =
                __float22bfloat162_rn(make_float2(c[mt][nt][2] + b0, c[mt][nt][3] + b1));
        }
    }
    __syncthreads();

    int pl = blockIdx.x;           // 0=q, 1..3=kt, 4..6=vt
    __nv_bfloat16* base;
    size_t stride;
    if (pl == 0)      { base = g_q; stride = 128; }
    else if (pl <= 3) { base = g_kv + (size_t)(pl - 1) * 256; stride = 768; }
    else              { base = g_kv + (size_t)(pl - 4) * 256 + 128; stride = 768; }

    #pragma unroll
    for (int i = 0; i < 8; i++) {
        int idx = t + i * 256;
        int row = idx >> 4, c8 = (idx & 15) << 3;
        uint4 v = *(const uint4*)(smh + row * EPI_STR + c8);
        *(uint4*)(base + (size_t)(row0 + row) * stride + c8) = v;
    }
}

// ---------------- out GEMM fused with skip-gate + LayerNorm -----------------
__global__ __launch_bounds__(256, 2) void k_gemm_out_ln(const float* __restrict__ bout_l,
                                                        const float* __restrict__ skipv, int l,
                                                        const float* __restrict__ gamma,
                                                        const float* __restrict__ beta) {
    extern __shared__ __nv_bfloat16 smh[];
    __shared__ float s_rs[128], s_rq[128], s_g[128], s_b[128], s_bias[128];
    unsigned int smb = (unsigned int)__cvta_generic_to_shared(smh);
    int t = threadIdx.x;
    int row0 = blockIdx.y * 128;

    GEMM_PIPELINE(g_aggb, g_Wrb, row0, 0)

    if (t < 128) {
        s_rs[t] = 0.f; s_rq[t] = 0.f;
        s_g[t] = gamma[t]; s_b[t] = beta[t]; s_bias[t] = bout_l[t];
    }
    __syncthreads();

    int wid = t >> 5, lane = t & 31;
    int wm = wid >> 2, wn = wid & 3;
    int gid = lane >> 2, tig = lane & 3;
    float c[4][4][4];
    #pragma unroll
    for (int mt = 0; mt < 4; mt++)
        #pragma unroll
        for (int nt = 0; nt < 4; nt++)
            #pragma unroll
            for (int q = 0; q < 4; q++) c[mt][nt][q] = 0.f;

    GEMM_MAINLOOP()

    float alpha = 1.f / (1.f + expf(-__ldg(skipv + l)));
    float rs_loc[8], rq_loc[8];
    #pragma unroll
    for (int i = 0; i < 8; i++) { rs_loc[i] = 0.f; rq_loc[i] = 0.f; }
    #pragma unroll
    for (int mt = 0; mt < 4; mt++) {
        int m0 = row0 + wm * 64 + mt * 16 + gid;
        #pragma unroll
        for (int nt = 0; nt < 4; nt++) {
            int cc = wn * 32 + nt * 8 + tig * 2;
            float b0 = s_bias[cc], b1 = s_bias[cc + 1];
            float2 h0 = __bfloat1622float2(*(const __nv_bfloat162*)(g_hb + (size_t)m0 * 128 + cc));
            float2 h1 = __bfloat1622float2(*(const __nv_bfloat162*)(g_hb + (size_t)(m0 + 8) * 128 + cc));
            c[mt][nt][0] = alpha * (c[mt][nt][0] + b0) + (1.f - alpha) * h0.x;
            c[mt][nt][1] = alpha * (c[mt][nt][1] + b1) + (1.f - alpha) * h0.y;
            c[mt][nt][2] = alpha * (c[mt][nt][2] + b0) + (1.f - alpha) * h1.x;
            c[mt][nt][3] = alpha * (c[mt][nt][3] + b1) + (1.f - alpha) * h1.y;
            rs_loc[mt * 2]     += c[mt][nt][0] + c[mt][nt][1];
            rs_loc[mt * 2 + 1] += c[mt][nt][2] + c[mt][nt][3];
            rq_loc[mt * 2]     += c[mt][nt][0] * c[mt][nt][0] + c[mt][nt][1] * c[mt][nt][1];
            rq_loc[mt * 2 + 1] += c[mt][nt][2] * c[mt][nt][2] + c[mt][nt][3] * c[mt][nt][3];
        }
    }
    #pragma unroll
    for (int i = 0; i < 8; i++) {
        rs_loc[i] += __shfl_xor_sync(0xffffffffu, rs_loc[i], 1);
        rs_loc[i] += __shfl_xor_sync(0xffffffffu, rs_loc[i], 2);
        rq_loc[i] += __shfl_xor_sync(0xffffffffu, rq_loc[i], 1);
        rq_loc[i] += __shfl_xor_sync(0xffffffffu, rq_loc[i], 2);
    }
    if (tig == 0) {
        #pragma unroll
        for (int mt = 0; mt < 4; mt++) {
            int rl = wm * 64 + mt * 16 + gid;
            atomicAdd(&s_rs[rl], rs_loc[mt * 2]);
            atomicAdd(&s_rq[rl], rq_loc[mt * 2]);
            atomicAdd(&s_rs[rl + 8], rs_loc[mt * 2 + 1]);
            atomicAdd(&s_rq[rl + 8], rq_loc[mt * 2 + 1]);
        }
    }
    __syncthreads();

    // normalize into smem stage, then coalesced uint4 writes to g_hb
    #pragma unroll
    for (int mt = 0; mt < 4; mt++) {
        int rl = wm * 64 + mt * 16 + gid;
        #pragma unroll
        for (int half = 0; half < 2; half++) {
            int r = rl + half * 8;
            float mu = s_rs[r] * (1.f / 128.f);
            float var = s_rq[r] * (1.f / 128.f) - mu * mu;
            float inv = rsqrtf(var + 1e-5f);
            #pragma unroll
            for (int nt = 0; nt < 4; nt++) {
                int cc = wn * 32 + nt * 8 + tig * 2;
                float v0 = (c[mt][nt][half * 2]     - mu) * inv * s_g[cc]     + s_b[cc];
                float v1 = (c[mt][nt][half * 2 + 1] - mu) * inv * s_g[cc + 1] + s_b[cc + 1];
                *(__nv_bfloat162*)(smh + r * EPI_STR + cc) =
                    __float22bfloat162_rn(make_float2(v0, v1));
            }
        }
    }
    __syncthreads();
    #pragma unroll
    for (int i = 0; i < 8; i++) {
        int idx = t + i * 256;
        int row = idx >> 4, c8 = (idx & 15) << 3;
        uint4 v = *(const uint4*)(smh + row * EPI_STR + c8);
        *(uint4*)(g_hb + (size_t)(row0 + row) * 128 + c8) = v;
    }
}

// ---------------- node-parallel aggregation: softmax + gelu fused -----------
// One warp per dst node; CSR entries preloaded cooperatively (coalesced) and
// broadcast by shuffle; kv gathers double-buffered.
__global__ __launch_bounds__(256) void k_agg(const float* __restrict__ prel) {
    int node = (int)((blockIdx.x * (size_t)blockDim.x + threadIdx.x) >> 5);
    int lane = threadIdx.x & 31;
    if (node >= NN) return;

    int h = lane >> 3;
    float p0 = __ldg(prel + 0 * 4 + h) * INV_SQRT_D;
    float p1 = __ldg(prel + 1 * 4 + h) * INV_SQRT_D;
    float p2 = __ldg(prel + 2 * 4 + h) * INV_SQRT_D;

    uint2 qraw = ((const uint2*)(g_q + (size_t)node * 128))[lane];
    float2 q0 = __bfloat1622float2(*(__nv_bfloat162*)&qraw.x);
    float2 q1 = __bfloat1622float2(*(__nv_bfloat162*)&qraw.y);

    int start = __ldg(&g_rowptr[node]);
    int deg   = __ldg(&g_deg[node]);

    float4 acc = make_float4(0.f, 0.f, 0.f, 0.f);
    float zl = 0.f;

    // fast path: entries for first min(deg,32) edges preloaded cooperatively
    int nfast = (deg < 32) ? deg : 32;
    int entry_l = (lane < nfast) ? __ldg(&g_eidx[start + lane]) : 0;

    uint2 krA, vrA, krB, vrB;
    int rA = 0, rB = 0;
    if (nfast > 0) {
        int entry = __shfl_sync(0xffffffffu, entry_l, 0);
        int src = entry & 0x3FFFF; rA = entry >> 18;
        const uint2* kvp = (const uint2*)(g_kv + (size_t)src * 768 + rA * 256);
        krA = kvp[lane]; vrA = kvp[lane + 32];
    }
    if (nfast > 1) {
        int entry = __shfl_sync(0xffffffffu, entry_l, 1);
        int src = entry & 0x3FFFF; rB = entry >> 18;
        const uint2* kvp = (const uint2*)(g_kv + (size_t)src * 768 + rB * 256);
        krB = kvp[lane]; vrB = kvp[lane + 32];
    }
    for (int j = 0; j < nfast; j++) {
        uint2 krc = krA, vrc = vrA;
        int rc = rA;
        // rotate: B -> A, prefetch j+2 -> B
        krA = krB; vrA = vrB; rA = rB;
        if (j + 2 < nfast) {
            int entry = __shfl_sync(0xffffffffu, entry_l, j + 2);
            int src = entry & 0x3FFFF; rB = entry >> 18;
            const uint2* kvp = (const uint2*)(g_kv + (size_t)src * 768 + rB * 256);
            krB = kvp[lane]; vrB = kvp[lane + 32];
        }
        float2 k0 = __bfloat1622float2(*(__nv_bfloat162*)&krc.x);
        float2 k1 = __bfloat1622float2(*(__nv_bfloat162*)&krc.y);
        float s = q0.x * k0.x + q0.y * k0.y + q1.x * k1.x + q1.y * k1.y;
        s += __shfl_down_sync(0xffffffffu, s, 4);
        s += __shfl_down_sync(0xffffffffu, s, 2);
        s += __shfl_down_sync(0xffffffffu, s, 1);
        float wv = 0.f;
        if ((lane & 7) == 0) {
            float p = (rc == 0) ? p0 : ((rc == 1) ? p1 : p2);
            wv = expf(s * p);
            zl += wv;
        }
        float w = __shfl_sync(0xffffffffu, wv, lane & 24);
        float2 v0 = __bfloat1622float2(*(__nv_bfloat162*)&vrc.x);
        float2 v1 = __bfloat1622float2(*(__nv_bfloat162*)&vrc.y);
        acc.x += w * v0.x; acc.y += w * v0.y;
        acc.z += w * v1.x; acc.w += w * v1.y;
    }
    // rare tail (deg > 32): simple sequential path
    for (int j = 32; j < deg; j++) {
        int entry = __ldg(&g_eidx[start + j]);
        int src = entry & 0x3FFFF; int rc = entry >> 18;
        const uint2* kvp = (const uint2*)(g_kv + (size_t)src * 768 + rc * 256);
        uint2 krc = kvp[lane], vrc = kvp[lane + 32];
        float2 k0 = __bfloat1622float2(*(__nv_bfloat162*)&krc.x);
        float2 k1 = __bfloat1622float2(*(__nv_bfloat162*)&krc.y);
        float s = q0.x * k0.x + q0.y * k0.y + q1.x * k1.x + q1.y * k1.y;
        s += __shfl_down_sync(0xffffffffu, s, 4);
        s += __shfl_down_sync(0xffffffffu, s, 2);
        s += __shfl_down_sync(0xffffffffu, s, 1);
        float wv = 0.f;
        if ((lane & 7) == 0) {
            float p = (rc == 0) ? p0 : ((rc == 1) ? p1 : p2);
            wv = expf(s * p);
            zl += wv;
        }
        float w = __shfl_sync(0xffffffffu, wv, lane & 24);
        float2 v0 = __bfloat1622float2(*(__nv_bfloat162*)&vrc.x);
        float2 v1 = __bfloat1622float2(*(__nv_bfloat162*)&vrc.y);
        acc.x += w * v0.x; acc.y += w * v0.y;
        acc.z += w * v1.x; acc.w += w * v1.y;
    }

    float z = __shfl_sync(0xffffffffu, zl, lane & 24);
    float inv = 1.f / (z + 1e-16f);
    float a0 = acc.x * inv, a1 = acc.y * inv, a2 = acc.z * inv, a3 = acc.w * inv;
    a0 = 0.5f * a0 * (1.f + erff(a0 * 0.70710678118654752f));
    a1 = 0.5f * a1 * (1.f + erff(a1 * 0.70710678118654752f));
    a2 = 0.5f * a2 * (1.f + erff(a2 * 0.70710678118654752f));
    a3 = 0.5f * a3 * (1.f + erff(a3 * 0.70710678118654752f));
    __nv_bfloat162 o0 = __float22bfloat162_rn(make_float2(a0, a1));
    __nv_bfloat162 o1 = __float22bfloat162_rn(make_float2(a2, a3));
    uint2 packed;
    packed.x = *(unsigned int*)&o0;
    packed.y = *(unsigned int*)&o1;
    ((uint2*)(g_aggb + (size_t)node * 128))[lane] = packed;
}

// ---------------- masked mean pooling (h in bf16) ---------------------------
__global__ void k_pool(const float* __restrict__ x, const int* __restrict__ batch) {
    int j = threadIdx.x;  // 128
    int chunk = (NN + gridDim.x - 1) / gridDim.x;
    int n0 = blockIdx.x * chunk;
    int n1 = n0 + chunk; if (n1 > NN) n1 = NN;
    if (n0 >= NN) return;
    float accw = 0.f, accn = 0.f, cw = 0.f, cn = 0.f;
    int cur = batch[n0];
    for (int n = n0; n < n1; n++) {
        int b = batch[n];
        if (b != cur) {
            atomicAdd(&g_poolsum[cur * 128 + j], accw);
            atomicAdd(&g_poolsum[(BBATCH + cur) * 128 + j], accn);
            if (j == 0) { atomicAdd(&g_poolcnt[cur], cw); atomicAdd(&g_poolcnt[BBATCH + cur], cn); }
            accw = accn = cw = cn = 0.f; cur = b;
        }
        float wv = (x[(size_t)n * 5 + 1] > 0.f) ? 1.f : 0.f;
        float hv = __bfloat162float(g_hb[(size_t)n * 128 + j]);
        accw += wv * hv; accn += (1.f - wv) * hv;
        cw += wv; cn += 1.f - wv;
    }
    atomicAdd(&g_poolsum[cur * 128 + j], accw);
    atomicAdd(&g_poolsum[(BBATCH + cur) * 128 + j], accn);
    if (j == 0) { atomicAdd(&g_poolcnt[cur], cw); atomicAdd(&g_poolcnt[BBATCH + cur], cn); }
}

// ---------------- classifier head -------------------------------------------
__global__ void k_head(const float* __restrict__ task, const float* __restrict__ Wtf,
                       const float* __restrict__ btf, const float* __restrict__ Wc1,
                       const float* __restrict__ bc1, const float* __restrict__ Wc2,
                       const float* __restrict__ bc2, float* __restrict__ out) {
    int b = blockIdx.x, t = threadIdx.x;  // 256 threads
    __shared__ float feat[640];
    __shared__ float t1[256];
    __shared__ float t2[64];
    if (t < 128) {
        float c  = g_poolcnt[b];
        float s  = g_poolsum[b * 128 + t];
        feat[t] = (c > 0.f) ? (s / fmaxf(c, 1.f)) : 0.f;
        float c2 = g_poolcnt[BBATCH + b];
        float s2 = g_poolsum[(BBATCH + b) * 128 + t];
        feat[128 + t] = (c2 > 0.f) ? (s2 / fmaxf(c2, 1.f)) : 0.f;
    }
    for (int i = t; i < 384; i += 256) feat[256 + i] = task[b * 384 + i];
    __syncthreads();
    float acc = btf[t];
    for (int i = 0; i < 640; i++) acc += feat[i] * Wtf[i * 256 + t];
    t1[t] = fmaxf(acc, 0.f);
    __syncthreads();
    if (t < 64) {
        float a2 = bc1[t];
        for (int i = 0; i < 256; i++) a2 += t1[i] * Wc1[i * 64 + t];
        t2[t] = fmaxf(a2, 0.f);
    }
    __syncthreads();
    if (t == 0) {
        float s = bc2[0];
        for (int i = 0; i < 64; i++) s += t2[i] * Wc2[i];
        out[b] = s;
    }
}

// ---------------- launcher ---------------------------------------------------
extern "C" void kernel_launch(void* const* d_in, const int* in_sizes, int n_in,
                              void* d_out, int out_size) {
    const float* x      = (const float*)d_in[0];
    const int*   ast    = (const int*)d_in[1];
    const int*   batch  = (const int*)d_in[2];
    const int*   ei0    = (const int*)d_in[3];
    const int*   ei1    = (const int*)d_in[4];
    const int*   ei2    = (const int*)d_in[5];
    const float* task   = (const float*)d_in[6];
    const float* emb    = (const float*)d_in[7];
    const float* Win    = (const float*)d_in[8];
    const float* binp   = (const float*)d_in[9];
    const float* Wkqv   = (const float*)d_in[10];
    const float* bkqv   = (const float*)d_in[11];
    const float* Wk_rel = (const float*)d_in[12];
    const float* Wv_rel = (const float*)d_in[13];
    const float* p_rel  = (const float*)d_in[14];
    const float* Wout   = (const float*)d_in[15];
    const float* bout   = (const float*)d_in[16];
    const float* skipv  = (const float*)d_in[17];
    const float* ln_g   = (const float*)d_in[18];
    const float* ln_b   = (const float*)d_in[19];
    const float* Wtf    = (const float*)d_in[20];
    const float* btf    = (const float*)d_in[21];
    const float* Wc1    = (const float*)d_in[22];
    const float* bc1    = (const float*)d_in[23];
    const float* Wc2    = (const float*)d_in[24];
    const float* bc2    = (const float*)d_in[25];
    float* out = (float*)d_out;

    cudaFuncSetAttribute(k_gemm_feat_tc, cudaFuncAttributeMaxDynamicSharedMemorySize, GEMM_SMEM);
    cudaFuncSetAttribute(k_gemm_out_ln,  cudaFuncAttributeMaxDynamicSharedMemorySize, GEMM_SMEM);

    k_embed<<<2048, 128>>>(x, ast, emb, Win, binp);

    // CSR build (edge structure constant across layers)
    k_csr_zero<<<(NN + 255) / 256, 256>>>();
    k_csr_hist<<<(NE3 + 255) / 256, 256>>>(ei0, ei1, ei2);
    k_csr_scan1<<<NB_SCAN, 256>>>();
    k_csr_scan2<<<1, 256>>>();
    k_csr_scan3<<<NB_SCAN, 256>>>();
    k_csr_fill<<<(NE3 + 255) / 256, 256>>>(ei0, ei1, ei2);

    for (int l = 0; l < 2; l++) {
        k_wcomp<<<1024, 128>>>(Wkqv, bkqv, Wk_rel, Wv_rel,
                               Wout + (size_t)l * 128 * 128, l);
        k_gemm_feat_tc<<<dim3(7, NP / 128), 256, GEMM_SMEM>>>();
        k_agg<<<(NN * 32 + 255) / 256, 256>>>(p_rel + l * 12);
        k_gemm_out_ln<<<dim3(1, NP / 128), 256, GEMM_SMEM>>>(
            bout + l * 128, skipv, l, ln_g + l * 128, ln_b + l * 128);
    }
    k_init_pool<<<33, 512>>>();
    k_pool<<<1024, 128>>>(x, batch);
    k_head<<<64, 256>>>(task, Wtf, btf, Wc1, bc1, Wc2, bc2, out);
}

// round 17
// speedup vs baseline: 1.0314x; 1.0314x over previous
#include <cuda_runtime.h>
#include <cuda_bf16.h>
#include <math.h>

#define NN      200000
#define NP      200192      // padded: 128*1564 for GEMM tiling
#define EE      300000
#define NE3     (3 * EE)
#define BBATCH  64
#define HIDDEN  128
#define NREL    3
#define NHEAD   4
#define F7      896         // q | kt0..2 | vt0..2  (7 * 128)
#define INV_SQRT_D 0.17677669529663687f
#define NB_SCAN 196         // ceil(NN / 1024)

// ---------------- scratch (device globals; no allocations allowed) ----------
__device__ __align__(16) __nv_bfloat16  g_hb[NP * HIDDEN];         // h (bf16 only)
__device__ __align__(16) __nv_bfloat16  g_q[(size_t)NP * 128];     // q (dst-indexed)
__device__ __align__(16) __nv_bfloat16  g_kv[(size_t)NP * 768];    // [node][rel][kt128|vt128]
__device__ __align__(16) __nv_bfloat16  g_aggb[NP * HIDDEN];       // gelu(agg) bf16
__device__ __align__(16) __nv_bfloat16  g_Wcb[F7 * HIDDEN];        // N-major bf16
__device__ __align__(16) __nv_bfloat16  g_Wrb[HIDDEN * HIDDEN];    // N-major bf16
__device__ float                        g_bc[F7];
__device__ float                        g_poolsum[2 * BBATCH * HIDDEN];
__device__ float                        g_poolcnt[2 * BBATCH];
// CSR (rebuilt every launch)
__device__ int                          g_deg[NN];
__device__ int                          g_rowptr[NN];
__device__ int                          g_cur[NN];
__device__ int                          g_bsum[256];
__device__ int                          g_eidx[NE3];               // src | rel<<18

// ---------------- input embedding -------------------------------------------
__global__ void k_embed(const float* __restrict__ x, const int* __restrict__ ast,
                        const float* __restrict__ emb, const float* __restrict__ Win,
                        const float* __restrict__ binp) {
    __shared__ float Ws[69 * 128];
    __shared__ float iv[69];
    for (int i = threadIdx.x; i < 69 * 128; i += blockDim.x) Ws[i] = Win[i];
    int j = threadIdx.x;  // 128 threads
    for (int n = blockIdx.x; n < NN; n += gridDim.x) {
        __syncthreads();
        if (j < 64)       iv[j] = emb[(size_t)ast[n] * 64 + j];
        else if (j < 69)  iv[j] = x[(size_t)n * 5 + (j - 64)];
        __syncthreads();
        float acc = binp[j];
        #pragma unroll
        for (int i = 0; i < 69; i++) acc += iv[i] * Ws[i * 128 + j];
        g_hb[(size_t)n * 128 + j] = __float2bfloat16(acc);
    }
}

// ---------------- composite weights + Wout transpose (merged) ---------------
__global__ void k_wcomp(const float* __restrict__ Wkqv, const float* __restrict__ bkqv,
                        const float* __restrict__ Wk_rel, const float* __restrict__ Wv_rel,
                        const float* __restrict__ Wout_l, int l) {
    int i = threadIdx.x;    // 0..127
    if (blockIdx.x >= 896) {               // tail 128 blocks: Wout transpose
        int bb = blockIdx.x - 896;         // k index
        g_Wrb[(size_t)i * 128 + bb] = __float2bfloat16(Wout_l[bb * 128 + i]);
        return;
    }
    int col = blockIdx.x;   // 0..895 (output col)
    const float* Wl = Wkqv + (size_t)l * 128 * 384;
    const float* bl = bkqv + l * 384;
    int pl = col >> 7;      // plane: 0=q, 1..3=kt, 4..6=vt
    float wv, bv;
    if (pl == 0) {
        wv = Wl[(size_t)i * 384 + 128 + col];
        bv = bl[128 + col];
    } else {
        int cc = col & 127, h = cc >> 5, f = cc & 31;
        int rel   = (pl <= 3) ? (pl - 1) : (pl - 4);
        int kvoff = (pl <= 3) ? 0 : 256;
        const float* Wr = ((pl <= 3) ? Wk_rel : Wv_rel) + (size_t)((l * 3 + rel) * 4 + h) * 1024;
        float acc = 0.f, bacc = 0.f;
        #pragma unroll
        for (int d = 0; d < 32; d++) {
            float wr = Wr[d * 32 + f];
            acc  += Wl[(size_t)i * 384 + kvoff + h * 32 + d] * wr;
            bacc += bl[kvoff + h * 32 + d] * wr;
        }
        wv = acc; bv = bacc;
    }
    g_Wcb[(size_t)col * 128 + i] = __float2bfloat16(wv);
    if (i == 0) g_bc[col] = bv;
}

__global__ void k_init_pool() {
    int i = blockIdx.x * blockDim.x + threadIdx.x;
    if (i < 2 * BBATCH * HIDDEN) g_poolsum[i] = 0.f;
    if (i < 2 * BBATCH) g_poolcnt[i] = 0.f;
}

// ---------------- CSR build (once per launch) --------------------------------
__global__ void k_csr_zero() {
    int i = blockIdx.x * blockDim.x + threadIdx.x;
    if (i < NN) g_deg[i] = 0;
}

__global__ void k_csr_hist(const int* __restrict__ ei0, const int* __restrict__ ei1,
                           const int* __restrict__ ei2) {
    int idx = blockIdx.x * blockDim.x + threadIdx.x;
    if (idx >= NE3) return;
    int r = idx / EE, e = idx - r * EE;
    const int* ei = (r == 0) ? ei0 : ((r == 1) ? ei1 : ei2);
    atomicAdd(&g_deg[__ldg(ei + EE + e)], 1);
}

__global__ void k_csr_scan1() {
    __shared__ int ss[256];
    int b = blockIdx.x, t = threadIdx.x;
    int base = b * 1024 + t * 4;
    int v[4], tot = 0;
    #pragma unroll
    for (int i = 0; i < 4; i++) {
        v[i] = (base + i < NN) ? g_deg[base + i] : 0;
        tot += v[i];
    }
    ss[t] = tot; __syncthreads();
    for (int off = 1; off < 256; off <<= 1) {
        int x = (t >= off) ? ss[t - off] : 0;
        __syncthreads();
        ss[t] += x;
        __syncthreads();
    }
    int run = ss[t] - tot;
    #pragma unroll
    for (int i = 0; i < 4; i++) {
        if (base + i < NN) g_rowptr[base + i] = run;
        run += v[i];
    }
    if (t == 255) g_bsum[b] = ss[255];
}

__global__ void k_csr_scan2() {
    __shared__ int ss[256];
    int t = threadIdx.x;
    int own = (t < NB_SCAN) ? g_bsum[t] : 0;
    ss[t] = own; __syncthreads();
    for (int off = 1; off < 256; off <<= 1) {
        int x = (t >= off) ? ss[t - off] : 0;
        __syncthreads();
        ss[t] += x;
        __syncthreads();
    }
    if (t < NB_SCAN) g_bsum[t] = ss[t] - own;
}

__global__ void k_csr_scan3() {
    int b = blockIdx.x, t = threadIdx.x;
    int off = g_bsum[b];
    int base = b * 1024 + t * 4;
    #pragma unroll
    for (int i = 0; i < 4; i++) {
        if (base + i < NN) {
            int rp = g_rowptr[base + i] + off;
            g_rowptr[base + i] = rp;
            g_cur[base + i] = rp;
        }
    }
}

__global__ void k_csr_fill(const int* __restrict__ ei0, const int* __restrict__ ei1,
                           const int* __restrict__ ei2) {
    int idx = blockIdx.x * blockDim.x + threadIdx.x;
    if (idx >= NE3) return;
    int r = idx / EE, e = idx - r * EE;
    const int* ei = (r == 0) ? ei0 : ((r == 1) ? ei1 : ei2);
    int src = __ldg(ei + e), dst = __ldg(ei + EE + e);
    int pos = atomicAdd(&g_cur[dst], 1);
    g_eidx[pos] = src | (r << 18);
}

// ---------------- pipelined BF16 tensor-core GEMM core ----------------------
#define BK    32
#define HSTR  40
#define SA_H  (128 * HSTR)
#define SB_H  (128 * HSTR)
#define SB_OFF (4 * SA_H)
#define GEMM_SMEM ((SB_OFF + 4 * SB_H) * 2) // 81920 B
#define EPI_STR 136                          // epilogue staging stride (halves)

__device__ __forceinline__ void mma_bf16(float c[4], const unsigned int a[4],
                                         const unsigned int b[2]) {
    asm volatile(
        "mma.sync.aligned.m16n8k16.row.col.f32.bf16.bf16.f32 "
        "{%0,%1,%2,%3}, {%4,%5,%6,%7}, {%8,%9}, {%0,%1,%2,%3};"
        : "+f"(c[0]), "+f"(c[1]), "+f"(c[2]), "+f"(c[3])
        : "r"(a[0]), "r"(a[1]), "r"(a[2]), "r"(a[3]), "r"(b[0]), "r"(b[1]));
}
__device__ __forceinline__ void cpasync16(unsigned int dst, const void* src) {
    asm volatile("cp.async.cg.shared.global [%0], [%1], 16;" :: "r"(dst), "l"(src));
}
#define CP_COMMIT() asm volatile("cp.async.commit_group;")
#define CP_WAIT(N)  asm volatile("cp.async.wait_group %0;" :: "n"(N))

__device__ __forceinline__ void gemm_load_stage(unsigned int smb, int s, int kt,
                                                const __nv_bfloat16* __restrict__ A,
                                                const __nv_bfloat16* __restrict__ Bt,
                                                int row0, int col0, int t) {
    #pragma unroll
    for (int i = 0; i < 2; i++) {
        int idx = t + i * 256;
        int row = idx >> 2, c8 = (idx & 3) << 3;
        unsigned int dst = smb + (unsigned int)(s * SA_H + row * HSTR + c8) * 2u;
        cpasync16(dst, A + (size_t)(row0 + row) * 128 + kt * BK + c8);
    }
    #pragma unroll
    for (int i = 0; i < 2; i++) {
        int idx = t + i * 256;
        int row = idx >> 2, c8 = (idx & 3) << 3;
        unsigned int dst = smb + (unsigned int)(SB_OFF + s * SB_H + row * HSTR + c8) * 2u;
        cpasync16(dst, Bt + (size_t)(col0 + row) * 128 + kt * BK + c8);
    }
    CP_COMMIT();
}

__device__ __forceinline__ void gemm_compute_stage(const __nv_bfloat16* __restrict__ sm,
                                                   int s, int wm, int wn, int gid, int tig,
                                                   float c[4][4][4]) {
    const __nv_bfloat16* As = sm + s * SA_H;
    const __nv_bfloat16* Bs = sm + SB_OFF + s * SB_H;
    #pragma unroll
    for (int k16 = 0; k16 < 2; k16++) {
        int kk = k16 * 16;
        unsigned int a[4][4];
        #pragma unroll
        for (int mt = 0; mt < 4; mt++) {
            int m0 = wm * 64 + mt * 16 + gid;
            a[mt][0] = *(const unsigned int*)(As + m0 * HSTR + kk + tig * 2);
            a[mt][1] = *(const unsigned int*)(As + (m0 + 8) * HSTR + kk + tig * 2);
            a[mt][2] = *(const unsigned int*)(As + m0 * HSTR + kk + 8 + tig * 2);
            a[mt][3] = *(const unsigned int*)(As + (m0 + 8) * HSTR + kk + 8 + tig * 2);
        }
        unsigned int b[4][2];
        #pragma unroll
        for (int nt = 0; nt < 4; nt++) {
            int n0 = wn * 32 + nt * 8 + gid;
            b[nt][0] = *(const unsigned int*)(Bs + n0 * HSTR + kk + tig * 2);
            b[nt][1] = *(const unsigned int*)(Bs + n0 * HSTR + kk + 8 + tig * 2);
        }
        #pragma unroll
        for (int mt = 0; mt < 4; mt++)
            #pragma unroll
            for (int nt = 0; nt < 4; nt++)
                mma_bf16(c[mt][nt], a[mt], b[nt]);
    }
}

#define GEMM_PIPELINE(A, Bt, row0, col0)                                   \
    gemm_load_stage(smb, 0, 0, A, Bt, row0, col0, t);                      \
    gemm_load_stage(smb, 1, 1, A, Bt, row0, col0, t);                      \
    gemm_load_stage(smb, 2, 2, A, Bt, row0, col0, t);                      \
    gemm_load_stage(smb, 3, 3, A, Bt, row0, col0, t);

#define GEMM_MAINLOOP()                                                    \
    CP_WAIT(3); __syncthreads(); gemm_compute_stage(smh, 0, wm, wn, gid, tig, c); \
    CP_WAIT(2); __syncthreads(); gemm_compute_stage(smh, 1, wm, wn, gid, tig, c); \
    CP_WAIT(1); __syncthreads(); gemm_compute_stage(smh, 2, wm, wn, gid, tig, c); \
    CP_WAIT(0); __syncthreads(); gemm_compute_stage(smh, 3, wm, wn, gid, tig, c);

// ---------------- feat GEMM: h@Wc -> q/kt/vt planes --------------------------
__global__ __launch_bounds__(256, 2) void k_gemm_feat_tc() {
    extern __shared__ __nv_bfloat16 smh[];
    __shared__ float s_bias[128];
    unsigned int smb = (unsigned int)__cvta_generic_to_shared(smh);
    int t = threadIdx.x;
    int row0 = blockIdx.y * 128;
    int col0 = blockIdx.x * 128;

    GEMM_PIPELINE(g_hb, g_Wcb, row0, col0)

    if (t < 128) s_bias[t] = g_bc[col0 + t];

    int wid = t >> 5, lane = t & 31;
    int wm = wid >> 2, wn = wid & 3;
    int gid = lane >> 2, tig = lane & 3;
    float c[4][4][4];
    #pragma unroll
    for (int mt = 0; mt < 4; mt++)
        #pragma unroll
        for (int nt = 0; nt < 4; nt++)
            #pragma unroll
            for (int q = 0; q < 4; q++) c[mt][nt][q] = 0.f;

    GEMM_MAINLOOP()

    // epilogue: stage in smem -> coalesced uint4 writes
    __syncthreads();
    #pragma unroll
    for (int mt = 0; mt < 4; mt++) {
        #pragma unroll
        for (int nt = 0; nt < 4; nt++) {
            int rloc = wm * 64 + mt * 16 + gid;
            int cc = wn * 32 + nt * 8 + tig * 2;
            float b0 = s_bias[cc], b1 = s_bias[cc + 1];
            *(__nv_bfloat162*)(smh + rloc * EPI_STR + cc) =
                __float22bfloat162_rn(make_float2(c[mt][nt][0] + b0, c[mt][nt][1] + b1));
            *(__nv_bfloat162*)(smh + (rloc + 8) * EPI_STR + cc) =
                __float22bfloat162_rn(make_float2(c[mt][nt][2] + b0, c[mt][nt][3] + b1));
        }
    }
    __syncthreads();

    int pl = blockIdx.x;           // 0=q, 1..3=kt, 4..6=vt
    __nv_bfloat16* base;
    size_t stride;
    if (pl == 0)      { base = g_q; stride = 128; }
    else if (pl <= 3) { base = g_kv + (size_t)(pl - 1) * 256; stride = 768; }
    else              { base = g_kv + (size_t)(pl - 4) * 256 + 128; stride = 768; }

    #pragma unroll
    for (int i = 0; i < 8; i++) {
        int idx = t + i * 256;
        int row = idx >> 4, c8 = (idx & 15) << 3;
        uint4 v = *(const uint4*)(smh + row * EPI_STR + c8);
        *(uint4*)(base + (size_t)(row0 + row) * stride + c8) = v;
    }
}

// ---------------- out GEMM fused with skip-gate + LayerNorm -----------------
__global__ __launch_bounds__(256, 2) void k_gemm_out_ln(const float* __restrict__ bout_l,
                                                        const float* __restrict__ skipv, int l,
                                                        const float* __restrict__ gamma,
                                                        const float* __restrict__ beta) {
    extern __shared__ __nv_bfloat16 smh[];
    __shared__ float s_rs[128], s_rq[128], s_g[128], s_b[128], s_bias[128];
    unsigned int smb = (unsigned int)__cvta_generic_to_shared(smh);
    int t = threadIdx.x;
    int row0 = blockIdx.y * 128;

    GEMM_PIPELINE(g_aggb, g_Wrb, row0, 0)

    if (t < 128) {
        s_rs[t] = 0.f; s_rq[t] = 0.f;
        s_g[t] = gamma[t]; s_b[t] = beta[t]; s_bias[t] = bout_l[t];
    }
    __syncthreads();

    int wid = t >> 5, lane = t & 31;
    int wm = wid >> 2, wn = wid & 3;
    int gid = lane >> 2, tig = lane & 3;
    float c[4][4][4];
    #pragma unroll
    for (int mt = 0; mt < 4; mt++)
        #pragma unroll
        for (int nt = 0; nt < 4; nt++)
            #pragma unroll
            for (int q = 0; q < 4; q++) c[mt][nt][q] = 0.f;

    GEMM_MAINLOOP()

    float alpha = 1.f / (1.f + expf(-__ldg(skipv + l)));
    float rs_loc[8], rq_loc[8];
    #pragma unroll
    for (int i = 0; i < 8; i++) { rs_loc[i] = 0.f; rq_loc[i] = 0.f; }
    #pragma unroll
    for (int mt = 0; mt < 4; mt++) {
        int m0 = row0 + wm * 64 + mt * 16 + gid;
        #pragma unroll
        for (int nt = 0; nt < 4; nt++) {
            int cc = wn * 32 + nt * 8 + tig * 2;
            float b0 = s_bias[cc], b1 = s_bias[cc + 1];
            float2 h0 = __bfloat1622float2(*(const __nv_bfloat162*)(g_hb + (size_t)m0 * 128 + cc));
            float2 h1 = __bfloat1622float2(*(const __nv_bfloat162*)(g_hb + (size_t)(m0 + 8) * 128 + cc));
            c[mt][nt][0] = alpha * (c[mt][nt][0] + b0) + (1.f - alpha) * h0.x;
            c[mt][nt][1] = alpha * (c[mt][nt][1] + b1) + (1.f - alpha) * h0.y;
            c[mt][nt][2] = alpha * (c[mt][nt][2] + b0) + (1.f - alpha) * h1.x;
            c[mt][nt][3] = alpha * (c[mt][nt][3] + b1) + (1.f - alpha) * h1.y;
            rs_loc[mt * 2]     += c[mt][nt][0] + c[mt][nt][1];
            rs_loc[mt * 2 + 1] += c[mt][nt][2] + c[mt][nt][3];
            rq_loc[mt * 2]     += c[mt][nt][0] * c[mt][nt][0] + c[mt][nt][1] * c[mt][nt][1];
            rq_loc[mt * 2 + 1] += c[mt][nt][2] * c[mt][nt][2] + c[mt][nt][3] * c[mt][nt][3];
        }
    }
    #pragma unroll
    for (int i = 0; i < 8; i++) {
        rs_loc[i] += __shfl_xor_sync(0xffffffffu, rs_loc[i], 1);
        rs_loc[i] += __shfl_xor_sync(0xffffffffu, rs_loc[i], 2);
        rq_loc[i] += __shfl_xor_sync(0xffffffffu, rq_loc[i], 1);
        rq_loc[i] += __shfl_xor_sync(0xffffffffu, rq_loc[i], 2);
    }
    if (tig == 0) {
        #pragma unroll
        for (int mt = 0; mt < 4; mt++) {
            int rl = wm * 64 + mt * 16 + gid;
            atomicAdd(&s_rs[rl], rs_loc[mt * 2]);
            atomicAdd(&s_rq[rl], rq_loc[mt * 2]);
            atomicAdd(&s_rs[rl + 8], rs_loc[mt * 2 + 1]);
            atomicAdd(&s_rq[rl + 8], rq_loc[mt * 2 + 1]);
        }
    }
    __syncthreads();

    // normalize into smem stage, then coalesced uint4 writes to g_hb
    #pragma unroll
    for (int mt = 0; mt < 4; mt++) {
        int rl = wm * 64 + mt * 16 + gid;
        #pragma unroll
        for (int half = 0; half < 2; half++) {
            int r = rl + half * 8;
            float mu = s_rs[r] * (1.f / 128.f);
            float var = s_rq[r] * (1.f / 128.f) - mu * mu;
            float inv = rsqrtf(var + 1e-5f);
            #pragma unroll
            for (int nt = 0; nt < 4; nt++) {
                int cc = wn * 32 + nt * 8 + tig * 2;
                float v0 = (c[mt][nt][half * 2]     - mu) * inv * s_g[cc]     + s_b[cc];
                float v1 = (c[mt][nt][half * 2 + 1] - mu) * inv * s_g[cc + 1] + s_b[cc + 1];
                *(__nv_bfloat162*)(smh + r * EPI_STR + cc) =
                    __float22bfloat162_rn(make_float2(v0, v1));
            }
        }
    }
    __syncthreads();
    #pragma unroll
    for (int i = 0; i < 8; i++) {
        int idx = t + i * 256;
        int row = idx >> 4, c8 = (idx & 15) << 3;
        uint4 v = *(const uint4*)(smh + row * EPI_STR + c8);
        *(uint4*)(g_hb + (size_t)(row0 + row) * 128 + c8) = v;
    }
}

// ---------------- node-parallel aggregation (R14 version: simple pipeline) ---
__global__ __launch_bounds__(256) void k_agg(const float* __restrict__ prel) {
    int node = (int)((blockIdx.x * (size_t)blockDim.x + threadIdx.x) >> 5);
    int lane = threadIdx.x & 31;
    if (node >= NN) return;

    int h = lane >> 3;
    float p0 = __ldg(prel + 0 * 4 + h) * INV_SQRT_D;
    float p1 = __ldg(prel + 1 * 4 + h) * INV_SQRT_D;
    float p2 = __ldg(prel + 2 * 4 + h) * INV_SQRT_D;

    uint2 qraw = ((const uint2*)(g_q + (size_t)node * 128))[lane];
    float2 q0 = __bfloat1622float2(*(__nv_bfloat162*)&qraw.x);
    float2 q1 = __bfloat1622float2(*(__nv_bfloat162*)&qraw.y);

    int start = __ldg(&g_rowptr[node]);
    int deg   = __ldg(&g_deg[node]);

    float4 acc = make_float4(0.f, 0.f, 0.f, 0.f);
    float zl = 0.f;

    uint2 kr, vr;
    int rcur = 0;
    if (deg > 0) {
        int entry = __ldg(&g_eidx[start]);
        int src = entry & 0x3FFFF; rcur = entry >> 18;
        const uint2* kvp = (const uint2*)(g_kv + (size_t)src * 768 + rcur * 256);
        kr = kvp[lane];
        vr = kvp[lane + 32];
    }
    for (int j = 0; j < deg; j++) {
        uint2 krc = kr, vrc = vr;
        int rc = rcur;
        if (j + 1 < deg) {
            int entry = __ldg(&g_eidx[start + j + 1]);
            int src = entry & 0x3FFFF; rcur = entry >> 18;
            const uint2* kvp = (const uint2*)(g_kv + (size_t)src * 768 + rcur * 256);
            kr = kvp[lane];
            vr = kvp[lane + 32];
        }
        float2 k0 = __bfloat1622float2(*(__nv_bfloat162*)&krc.x);
        float2 k1 = __bfloat1622float2(*(__nv_bfloat162*)&krc.y);
        float s = q0.x * k0.x + q0.y * k0.y + q1.x * k1.x + q1.y * k1.y;
        s += __shfl_down_sync(0xffffffffu, s, 4);
        s += __shfl_down_sync(0xffffffffu, s, 2);
        s += __shfl_down_sync(0xffffffffu, s, 1);
        float wv = 0.f;
        if ((lane & 7) == 0) {
            float p = (rc == 0) ? p0 : ((rc == 1) ? p1 : p2);
            wv = expf(s * p);
            zl += wv;
        }
        float w = __shfl_sync(0xffffffffu, wv, lane & 24);
        float2 v0 = __bfloat1622float2(*(__nv_bfloat162*)&vrc.x);
        float2 v1 = __bfloat1622float2(*(__nv_bfloat162*)&vrc.y);
        acc.x += w * v0.x; acc.y += w * v0.y;
        acc.z += w * v1.x; acc.w += w * v1.y;
    }

    float z = __shfl_sync(0xffffffffu, zl, lane & 24);
    float inv = 1.f / (z + 1e-16f);
    float a0 = acc.x * inv, a1 = acc.y * inv, a2 = acc.z * inv, a3 = acc.w * inv;
    a0 = 0.5f * a0 * (1.f + erff(a0 * 0.70710678118654752f));
    a1 = 0.5f * a1 * (1.f + erff(a1 * 0.70710678118654752f));
    a2 = 0.5f * a2 * (1.f + erff(a2 * 0.70710678118654752f));
    a3 = 0.5f * a3 * (1.f + erff(a3 * 0.70710678118654752f));
    __nv_bfloat162 o0 = __float22bfloat162_rn(make_float2(a0, a1));
    __nv_bfloat162 o1 = __float22bfloat162_rn(make_float2(a2, a3));
    uint2 packed;
    packed.x = *(unsigned int*)&o0;
    packed.y = *(unsigned int*)&o1;
    ((uint2*)(g_aggb + (size_t)node * 128))[lane] = packed;
}

// ---------------- masked mean pooling (h in bf16) ---------------------------
__global__ void k_pool(const float* __restrict__ x, const int* __restrict__ batch) {
    int j = threadIdx.x;  // 128
    int chunk = (NN + gridDim.x - 1) / gridDim.x;
    int n0 = blockIdx.x * chunk;
    int n1 = n0 + chunk; if (n1 > NN) n1 = NN;
    if (n0 >= NN) return;
    float accw = 0.f, accn = 0.f, cw = 0.f, cn = 0.f;
    int cur = batch[n0];
    for (int n = n0; n < n1; n++) {
        int b = batch[n];
        if (b != cur) {
            atomicAdd(&g_poolsum[cur * 128 + j], accw);
            atomicAdd(&g_poolsum[(BBATCH + cur) * 128 + j], accn);
            if (j == 0) { atomicAdd(&g_poolcnt[cur], cw); atomicAdd(&g_poolcnt[BBATCH + cur], cn); }
            accw = accn = cw = cn = 0.f; cur = b;
        }
        float wv = (x[(size_t)n * 5 + 1] > 0.f) ? 1.f : 0.f;
        float hv = __bfloat162float(g_hb[(size_t)n * 128 + j]);
        accw += wv * hv; accn += (1.f - wv) * hv;
        cw += wv; cn += 1.f - wv;
    }
    atomicAdd(&g_poolsum[cur * 128 + j], accw);
    atomicAdd(&g_poolsum[(BBATCH + cur) * 128 + j], accn);
    if (j == 0) { atomicAdd(&g_poolcnt[cur], cw); atomicAdd(&g_poolcnt[BBATCH + cur], cn); }
}

// ---------------- classifier head -------------------------------------------
__global__ void k_head(const float* __restrict__ task, const float* __restrict__ Wtf,
                       const float* __restrict__ btf, const float* __restrict__ Wc1,
                       const float* __restrict__ bc1, const float* __restrict__ Wc2,
                       const float* __restrict__ bc2, float* __restrict__ out) {
    int b = blockIdx.x, t = threadIdx.x;  // 256 threads
    __shared__ float feat[640];
    __shared__ float t1[256];
    __shared__ float t2[64];
    if (t < 128) {
        float c  = g_poolcnt[b];
        float s  = g_poolsum[b * 128 + t];
        feat[t] = (c > 0.f) ? (s / fmaxf(c, 1.f)) : 0.f;
        float c2 = g_poolcnt[BBATCH + b];
        float s2 = g_poolsum[(BBATCH + b) * 128 + t];
        feat[128 + t] = (c2 > 0.f) ? (s2 / fmaxf(c2, 1.f)) : 0.f;
    }
    for (int i = t; i < 384; i += 256) feat[256 + i] = task[b * 384 + i];
    __syncthreads();
    float acc = btf[t];
    for (int i = 0; i < 640; i++) acc += feat[i] * Wtf[i * 256 + t];
    t1[t] = fmaxf(acc, 0.f);
    __syncthreads();
    if (t < 64) {
        float a2 = bc1[t];
        for (int i = 0; i < 256; i++) a2 += t1[i] * Wc1[i * 64 + t];
        t2[t] = fmaxf(a2, 0.f);
    }
    __syncthreads();
    if (t == 0) {
        float s = bc2[0];
        for (int i = 0; i < 64; i++) s += t2[i] * Wc2[i];
        out[b] = s;
    }
}

// ---------------- launcher ---------------------------------------------------
extern "C" void kernel_launch(void* const* d_in, const int* in_sizes, int n_in,
                              void* d_out, int out_size) {
    const float* x      = (const float*)d_in[0];
    const int*   ast    = (const int*)d_in[1];
    const int*   batch  = (const int*)d_in[2];
    const int*   ei0    = (const int*)d_in[3];
    const int*   ei1    = (const int*)d_in[4];
    const int*   ei2    = (const int*)d_in[5];
    const float* task   = (const float*)d_in[6];
    const float* emb    = (const float*)d_in[7];
    const float* Win    = (const float*)d_in[8];
    const float* binp   = (const float*)d_in[9];
    const float* Wkqv   = (const float*)d_in[10];
    const float* bkqv   = (const float*)d_in[11];
    const float* Wk_rel = (const float*)d_in[12];
    const float* Wv_rel = (const float*)d_in[13];
    const float* p_rel  = (const float*)d_in[14];
    const float* Wout   = (const float*)d_in[15];
    const float* bout   = (const float*)d_in[16];
    const float* skipv  = (const float*)d_in[17];
    const float* ln_g   = (const float*)d_in[18];
    const float* ln_b   = (const float*)d_in[19];
    const float* Wtf    = (const float*)d_in[20];
    const float* btf    = (const float*)d_in[21];
    const float* Wc1    = (const float*)d_in[22];
    const float* bc1    = (const float*)d_in[23];
    const float* Wc2    = (const float*)d_in[24];
    const float* bc2    = (const float*)d_in[25];
    float* out = (float*)d_out;

    cudaFuncSetAttribute(k_gemm_feat_tc, cudaFuncAttributeMaxDynamicSharedMemorySize, GEMM_SMEM);
    cudaFuncSetAttribute(k_gemm_out_ln,  cudaFuncAttributeMaxDynamicSharedMemorySize, GEMM_SMEM);

    k_embed<<<2048, 128>>>(x, ast, emb, Win, binp);

    // CSR build (edge structure constant across layers)
    k_csr_zero<<<(NN + 255) / 256, 256>>>();
    k_csr_hist<<<(NE3 + 255) / 256, 256>>>(ei0, ei1, ei2);
    k_csr_scan1<<<NB_SCAN, 256>>>();
    k_csr_scan2<<<1, 256>>>();
    k_csr_scan3<<<NB_SCAN, 256>>>();
    k_csr_fill<<<(NE3 + 255) / 256, 256>>>(ei0, ei1, ei2);

    for (int l = 0; l < 2; l++) {
        k_wcomp<<<1024, 128>>>(Wkqv, bkqv, Wk_rel, Wv_rel,
                               Wout + (size_t)l * 128 * 128, l);
        k_gemm_feat_tc<<<dim3(7, NP / 128), 256, GEMM_SMEM>>>();
        k_agg<<<(NN * 32 + 255) / 256, 256>>>(p_rel + l * 12);
        k_gemm_out_ln<<<dim3(1, NP / 128), 256, GEMM_SMEM>>>(
            bout + l * 128, skipv, l, ln_g + l * 128, ln_b + l * 128);
    }
    k_init_pool<<<33, 512>>>();
    k_pool<<<1024, 128>>>(x, batch);
    k_head<<<64, 256>>>(task, Wtf, btf, Wc1, bc1, Wc2, bc2, out);
}